// round 1
// baseline (speedup 1.0000x reference)
#include <cuda_runtime.h>
#include <math.h>

// Problem sizes (fixed): B=4, T=2048, E=1024, M=2048; rows R = B*T = 8192.
#define R_ROWS 8192
#define E_DIM  1024
#define M_DIM  2048

#define BM 128
#define BN 128
#define BK 8
#define TM 8
#define TN 8

#define NCHUNK 16
#define TCH    128   // 2048 / 16

// -------- scratch (device globals; no allocation allowed) --------
__device__ float g_y [R_ROWS * E_DIM];   // LN1 output
__device__ float g_b0[R_ROWS * M_DIM];   // raw y@wi  (later: z@fwi)
__device__ float g_b1[R_ROWS * M_DIM];   // sigmoid(y@wig+b) (later: sigmoid(z@fwg+b))
__device__ float g_r [R_ROWS * M_DIM];   // sigmoid(y@wf+b)
__device__ float g_og[R_ROWS * M_DIM];   // sigmoid(y@wog+b)
__device__ float g_g [R_ROWS * M_DIM];   // softsign(h)*og
__device__ float g_x2[R_ROWS * E_DIM];   // x + g@wo
__device__ float g_z [R_ROWS * E_DIM];   // LN2 output
__device__ float g_Ac[NCHUNK * 8192];
__device__ float g_Sc[NCHUNK * 8192];
__device__ float g_Hc[NCHUNK * 8192];

__device__ __forceinline__ float sigm(float x) { return 1.f / (1.f + __expf(-x)); }

// -------- LayerNorm over rows of exactly 1024 floats --------
__global__ __launch_bounds__(256) void ln1024(const float* __restrict__ x,
                                              const float* __restrict__ w,
                                              const float* __restrict__ b,
                                              float* __restrict__ y) {
    int row = blockIdx.x;
    const float4* xr = (const float4*)(x + (size_t)row * 1024);
    float4 v = xr[threadIdx.x];
    float s = v.x + v.y + v.z + v.w;
    float q = v.x * v.x + v.y * v.y + v.z * v.z + v.w * v.w;
#pragma unroll
    for (int o = 16; o; o >>= 1) {
        s += __shfl_xor_sync(0xFFFFFFFF, s, o);
        q += __shfl_xor_sync(0xFFFFFFFF, q, o);
    }
    __shared__ float ss[8], sq[8];
    int wid = threadIdx.x >> 5, lane = threadIdx.x & 31;
    if (lane == 0) { ss[wid] = s; sq[wid] = q; }
    __syncthreads();
    s = 0.f; q = 0.f;
#pragma unroll
    for (int i = 0; i < 8; i++) { s += ss[i]; q += sq[i]; }
    float mu  = s * (1.f / 1024.f);
    float var = q * (1.f / 1024.f) - mu * mu;
    float inv = rsqrtf(var + 1e-5f);
    float4 wv = ((const float4*)w)[threadIdx.x];
    float4 bv = ((const float4*)b)[threadIdx.x];
    float4 o;
    o.x = (v.x - mu) * inv * wv.x + bv.x;
    o.y = (v.y - mu) * inv * wv.y + bv.y;
    o.z = (v.z - mu) * inv * wv.z + bv.z;
    o.w = (v.w - mu) * inv * wv.w + bv.w;
    ((float4*)(y + (size_t)row * 1024))[threadIdx.x] = o;
}

// -------- generic fp32 tiled GEMM: C = epi(A (*A2) @ B) --------
// A:[M,K] rm, B:[K,N] rm. Epilogue: +bias[N], optional sigmoid, +resid[M,N].
__global__ __launch_bounds__(256) void sgemm(const float* __restrict__ A,
                                             const float* __restrict__ A2,
                                             const float* __restrict__ B,
                                             const float* __restrict__ bias,
                                             const float* __restrict__ resid,
                                             float* __restrict__ C,
                                             int M, int N, int K, int act) {
    __shared__ float As[BK][BM];
    __shared__ float Bs[BK][BN];
    int tid  = threadIdx.x;
    int brow = blockIdx.y * BM, bcol = blockIdx.x * BN;
    int aRow = tid >> 1,  aCol = (tid & 1)  * 4;
    int bRow = tid >> 5,  bCol = (tid & 31) * 4;
    const float* Ap  = A + (size_t)(brow + aRow) * K + aCol;
    const float* A2p = A2 ? A2 + (size_t)(brow + aRow) * K + aCol : nullptr;
    const float* Bp  = B + (size_t)bRow * N + bcol + bCol;

    float acc[TM][TN];
#pragma unroll
    for (int i = 0; i < TM; i++)
#pragma unroll
        for (int j = 0; j < TN; j++) acc[i][j] = 0.f;

    int tx = tid & 15, ty = tid >> 4;

    for (int k0 = 0; k0 < K; k0 += BK) {
        float4 av = *(const float4*)(Ap + k0);
        if (A2p) {
            float4 a2 = *(const float4*)(A2p + k0);
            av.x *= a2.x; av.y *= a2.y; av.z *= a2.z; av.w *= a2.w;
        }
        float4 bv = *(const float4*)(Bp + (size_t)k0 * N);
        As[aCol + 0][aRow] = av.x;
        As[aCol + 1][aRow] = av.y;
        As[aCol + 2][aRow] = av.z;
        As[aCol + 3][aRow] = av.w;
        *(float4*)&Bs[bRow][bCol] = bv;
        __syncthreads();
#pragma unroll
        for (int kk = 0; kk < BK; kk++) {
            float af[TM], bf[TN];
            *(float4*)(af)     = *(const float4*)&As[kk][ty * TM];
            *(float4*)(af + 4) = *(const float4*)&As[kk][ty * TM + 4];
            *(float4*)(bf)     = *(const float4*)&Bs[kk][tx * TN];
            *(float4*)(bf + 4) = *(const float4*)&Bs[kk][tx * TN + 4];
#pragma unroll
            for (int i = 0; i < TM; i++)
#pragma unroll
                for (int j = 0; j < TN; j++)
                    acc[i][j] = fmaf(af[i], bf[j], acc[i][j]);
        }
        __syncthreads();
    }

    int col0 = bcol + tx * TN;
#pragma unroll
    for (int i = 0; i < TM; i++) {
        int row = brow + ty * TM + i;
#pragma unroll
        for (int jv = 0; jv < 2; jv++) {
            float4 c;
            c.x = acc[i][jv * 4 + 0];
            c.y = acc[i][jv * 4 + 1];
            c.z = acc[i][jv * 4 + 2];
            c.w = acc[i][jv * 4 + 3];
            if (bias) {
                float4 bb = *(const float4*)(bias + col0 + jv * 4);
                c.x += bb.x; c.y += bb.y; c.z += bb.z; c.w += bb.w;
            }
            if (act) { c.x = sigm(c.x); c.y = sigm(c.y); c.z = sigm(c.z); c.w = sigm(c.w); }
            if (resid) {
                float4 rr = *(const float4*)(resid + (size_t)row * N + col0 + jv * 4);
                c.x += rr.x; c.y += rr.y; c.z += rr.z; c.w += rr.w;
            }
            *(float4*)(C + (size_t)row * N + col0 + jv * 4) = c;
        }
    }
}

// -------- chunked linear-recurrence scan: h_t = r_t*h_{t-1} + yi_t --------
// Channels ch = b*M + m (8192 total). yi = b0*b1 computed on the fly.
__global__ __launch_bounds__(256) void scan_pass1(const float* __restrict__ b0,
                                                  const float* __restrict__ b1,
                                                  const float* __restrict__ rb,
                                                  float* __restrict__ Ac,
                                                  float* __restrict__ Sc) {
    int idx = blockIdx.x * 256 + threadIdx.x;      // c*8192 + ch
    int ch  = idx & 8191;
    int c   = idx >> 13;
    int b   = ch >> 11;
    int base = (b * 2048 + c * TCH) * 2048 + (ch & 2047);
    float A = 1.f, S = 0.f;
#pragma unroll 4
    for (int t = 0; t < TCH; t++) {
        float yi = b0[base] * b1[base];
        float rr = rb[base];
        S = fmaf(rr, S, yi);
        A *= rr;
        base += 2048;
    }
    Ac[idx] = A;
    Sc[idx] = S;
}

__global__ __launch_bounds__(256) void scan_pass2(const float* __restrict__ mem,
                                                  const float* __restrict__ Ac,
                                                  const float* __restrict__ Sc,
                                                  float* __restrict__ Hc,
                                                  float* __restrict__ memout) {
    int ch = blockIdx.x * 256 + threadIdx.x;
    float h = mem[ch];
#pragma unroll
    for (int c = 0; c < NCHUNK; c++) {
        int i = c * 8192 + ch;
        Hc[i] = h;
        h = fmaf(Ac[i], h, Sc[i]);
    }
    memout[ch] = h;   // mem_out = h[:, -1]
}

__global__ __launch_bounds__(256) void scan_pass3(const float* __restrict__ b0,
                                                  const float* __restrict__ b1,
                                                  const float* __restrict__ rb,
                                                  const float* __restrict__ og,
                                                  const float* __restrict__ Hc,
                                                  float* __restrict__ g) {
    int idx = blockIdx.x * 256 + threadIdx.x;
    int ch  = idx & 8191;
    int c   = idx >> 13;
    int b   = ch >> 11;
    int base = (b * 2048 + c * TCH) * 2048 + (ch & 2047);
    float h = Hc[idx];
#pragma unroll 4
    for (int t = 0; t < TCH; t++) {
        float yi = b0[base] * b1[base];
        float rr = rb[base];
        h = fmaf(rr, h, yi);
        float s = h / (1.f + fabsf(h));   // soft_sign
        g[base] = s * og[base];
        base += 2048;
    }
}

extern "C" void kernel_launch(void* const* d_in, const int* in_sizes, int n_in,
                              void* d_out, int out_size) {
    const float* x    = (const float*)d_in[0];
    const float* mem  = (const float*)d_in[1];
    const float* ln1w = (const float*)d_in[2];
    const float* ln1b = (const float*)d_in[3];
    const float* wf   = (const float*)d_in[4];
    const float* wfb  = (const float*)d_in[5];
    const float* wi   = (const float*)d_in[6];
    const float* wig  = (const float*)d_in[7];
    const float* wigb = (const float*)d_in[8];
    const float* wog  = (const float*)d_in[9];
    const float* wogb = (const float*)d_in[10];
    const float* wo   = (const float*)d_in[11];
    const float* ln2w = (const float*)d_in[12];
    const float* ln2b = (const float*)d_in[13];
    const float* fwi  = (const float*)d_in[14];
    const float* fwg  = (const float*)d_in[15];
    const float* fwgb = (const float*)d_in[16];
    const float* fwo  = (const float*)d_in[17];
    const float* fwob = (const float*)d_in[18];
    float* out = (float*)d_out;

    float *y, *b0, *b1, *rb, *og, *g, *x2, *z, *Ac, *Sc, *Hc;
    cudaGetSymbolAddress((void**)&y,  g_y);
    cudaGetSymbolAddress((void**)&b0, g_b0);
    cudaGetSymbolAddress((void**)&b1, g_b1);
    cudaGetSymbolAddress((void**)&rb, g_r);
    cudaGetSymbolAddress((void**)&og, g_og);
    cudaGetSymbolAddress((void**)&g,  g_g);
    cudaGetSymbolAddress((void**)&x2, g_x2);
    cudaGetSymbolAddress((void**)&z,  g_z);
    cudaGetSymbolAddress((void**)&Ac, g_Ac);
    cudaGetSymbolAddress((void**)&Sc, g_Sc);
    cudaGetSymbolAddress((void**)&Hc, g_Hc);

    const int R = R_ROWS;
    dim3 blk(256);
    dim3 gM(M_DIM / BN, R / BM);   // N = 2048
    dim3 gE(E_DIM / BN, R / BM);   // N = 1024

    // y = LN1(x)
    ln1024<<<R, 256>>>(x, ln1w, ln1b, y);

    // four gate GEMMs from y
    sgemm<<<gM, blk>>>(y, nullptr, wi,  nullptr, nullptr, b0, R, M_DIM, E_DIM, 0);
    sgemm<<<gM, blk>>>(y, nullptr, wig, wigb,    nullptr, b1, R, M_DIM, E_DIM, 1);
    sgemm<<<gM, blk>>>(y, nullptr, wf,  wfb,     nullptr, rb, R, M_DIM, E_DIM, 1);
    sgemm<<<gM, blk>>>(y, nullptr, wog, wogb,    nullptr, og, R, M_DIM, E_DIM, 1);

    // chunked scan; writes mem_out tail of d_out; g = softsign(h)*og
    scan_pass1<<<NCHUNK * 8192 / 256, 256>>>(b0, b1, rb, Ac, Sc);
    scan_pass2<<<8192 / 256, 256>>>(mem, Ac, Sc, Hc, out + (size_t)R_ROWS * E_DIM);
    scan_pass3<<<NCHUNK * 8192 / 256, 256>>>(b0, b1, rb, og, Hc, g);

    // x2 = x + g @ wo
    sgemm<<<gE, blk>>>(g, nullptr, wo, nullptr, x, x2, R, E_DIM, M_DIM, 0);

    // z = LN2(x2)
    ln1024<<<R, 256>>>(x2, ln2w, ln2b, z);

    // FFN
    sgemm<<<gM, blk>>>(z, nullptr, fwi, nullptr, nullptr, b0, R, M_DIM, E_DIM, 0);
    sgemm<<<gM, blk>>>(z, nullptr, fwg, fwgb,    nullptr, b1, R, M_DIM, E_DIM, 1);
    // out = x2 + (b0*b1) @ fwo + fwob
    sgemm<<<gE, blk>>>(b0, b1, fwo, fwob, x2, out, R, E_DIM, M_DIM, 0);
}

// round 3
// speedup vs baseline: 2.8021x; 2.8021x over previous
#include <cuda_runtime.h>
#include <cstdint>
#include <math.h>

// Sizes fixed: B=4, T=2048, E=1024, M=2048; R = B*T = 8192.
#define R_ROWS 8192
#define E_DIM  1024
#define M_DIM  2048
#define NCHUNK 16
#define TCH    128

// ---------------- scratch ----------------
__device__ float g_y [R_ROWS * E_DIM];
__device__ float g_b0[R_ROWS * M_DIM];
__device__ float g_b1[R_ROWS * M_DIM];   // yi / zi (gated product)
__device__ float g_r [R_ROWS * M_DIM];
__device__ float g_og[R_ROWS * M_DIM];
__device__ float g_g [R_ROWS * M_DIM];
__device__ float g_x2[R_ROWS * E_DIM];
__device__ float g_z [R_ROWS * E_DIM];
__device__ float g_Ac[NCHUNK * 8192];
__device__ float g_Sc[NCHUNK * 8192];
__device__ float g_Hc[NCHUNK * 8192];

__device__ __forceinline__ float sigm(float x) { return 1.f / (1.f + __expf(-x)); }

__device__ __forceinline__ uint32_t smem_u32(const void* p) {
    uint32_t a;
    asm("{ .reg .u64 t; cvta.to.shared.u64 t, %1; cvt.u32.u64 %0, t; }" : "=r"(a) : "l"(p));
    return a;
}

#define CP_ASYNC16(dst, src) asm volatile("cp.async.cg.shared.global [%0], [%1], 16;" :: "r"(dst), "l"(src))
#define CP_COMMIT()          asm volatile("cp.async.commit_group;" ::: "memory")
#define CP_WAIT1()           asm volatile("cp.async.wait_group 1;" ::: "memory")

__device__ __forceinline__ uint32_t f2tf32(float v) {
    uint32_t r;
    asm("cvt.rna.tf32.f32 %0, %1;" : "=r"(r) : "f"(v));
    return r;
}

#define MMA_TF32(c, a, b)                                                      \
    asm volatile("mma.sync.aligned.m16n8k8.row.col.f32.tf32.tf32.f32 "         \
        "{%0,%1,%2,%3}, {%4,%5,%6,%7}, {%8,%9}, {%0,%1,%2,%3};"                \
        : "+f"((c)[0]), "+f"((c)[1]), "+f"((c)[2]), "+f"((c)[3])               \
        : "r"((a)[0]), "r"((a)[1]), "r"((a)[2]), "r"((a)[3]),                  \
          "r"((b)[0]), "r"((b)[1]))

// ---------------- LayerNorm (rows of 1024) ----------------
__global__ __launch_bounds__(256) void ln1024(const float* __restrict__ x,
                                              const float* __restrict__ w,
                                              const float* __restrict__ b,
                                              float* __restrict__ y) {
    int row = blockIdx.x;
    const float4* xr = (const float4*)(x + (size_t)row * 1024);
    float4 v = xr[threadIdx.x];
    float s = v.x + v.y + v.z + v.w;
    float q = v.x * v.x + v.y * v.y + v.z * v.z + v.w * v.w;
#pragma unroll
    for (int o = 16; o; o >>= 1) {
        s += __shfl_xor_sync(0xFFFFFFFF, s, o);
        q += __shfl_xor_sync(0xFFFFFFFF, q, o);
    }
    __shared__ float ss[8], sq[8];
    int wid = threadIdx.x >> 5, lane = threadIdx.x & 31;
    if (lane == 0) { ss[wid] = s; sq[wid] = q; }
    __syncthreads();
    s = 0.f; q = 0.f;
#pragma unroll
    for (int i = 0; i < 8; i++) { s += ss[i]; q += sq[i]; }
    float mu  = s * (1.f / 1024.f);
    float var = q * (1.f / 1024.f) - mu * mu;
    float inv = rsqrtf(var + 1e-5f);
    float4 wv = ((const float4*)w)[threadIdx.x];
    float4 bv = ((const float4*)b)[threadIdx.x];
    float4 o;
    o.x = (v.x - mu) * inv * wv.x + bv.x;
    o.y = (v.y - mu) * inv * wv.y + bv.y;
    o.z = (v.z - mu) * inv * wv.z + bv.z;
    o.w = (v.w - mu) * inv * wv.w + bv.w;
    ((float4*)(y + (size_t)row * 1024))[threadIdx.x] = o;
}

// ---------------- tf32 mma.sync GEMM ----------------
// C[m][n] = epi( sum_k A[m][k] * B[k][n] ),  A:[M,K] rm, B:[K,N] rm.
// mode 0: store   1: sigmoid(acc+bias)   2: resid*sigmoid(acc+bias)   3: acc(+bias)+resid
// Tiles: BM=128, BN=128, BK=32. 256 thr = 8 warps (4 m x 2 n), warp tile 32x64.
#define ASTRIDE 36    // words per A row (32 + 4 pad)
#define BSTRIDE 132   // words per B row (128 + 4 pad)
#define ASTAGE  (128 * ASTRIDE)          // 4608 words
#define BSTAGE  (32 * BSTRIDE)           // 4224 words
#define GSMEM   ((2 * ASTAGE + 2 * BSTAGE) * 4)   // 70656 bytes

__global__ __launch_bounds__(256, 2) void gemm_mma(const float* __restrict__ A,
                                                   const float* __restrict__ B,
                                                   const float* __restrict__ bias,
                                                   const float* __restrict__ resid,
                                                   float* __restrict__ C,
                                                   int K, int N, int mode) {
    extern __shared__ char smem[];
    float* sw = (float*)smem;
    uint32_t sbase = smem_u32(smem);

    int tid = threadIdx.x;
    int wid = tid >> 5, lane = tid & 31;
    int wm = wid & 3, wn = wid >> 2;
    int m0 = wm * 32, n0 = wn * 64;
    int grp = lane >> 2, ktid = lane & 3;
    int brow = blockIdx.y * 128, bcol = blockIdx.x * 128;

    // global src pointers (per-thread)
    const float* gA = A + (size_t)(brow + (tid >> 1)) * K + (tid & 1) * 16;
    const float* gB = B + (size_t)(tid >> 3) * N + bcol + (tid & 7) * 4;
    // smem dst (bytes)
    uint32_t dA = sbase + (uint32_t)(tid >> 1) * (ASTRIDE * 4) + (uint32_t)(tid & 1) * 64;
    uint32_t dB = sbase + 2u * ASTAGE * 4 + (uint32_t)(tid >> 3) * (BSTRIDE * 4) + (uint32_t)(tid & 7) * 16;

    float acc[2][8][4];
#pragma unroll
    for (int i = 0; i < 2; i++)
#pragma unroll
        for (int j = 0; j < 8; j++)
#pragma unroll
            for (int v = 0; v < 4; v++) acc[i][j][v] = 0.f;

    const int nk = K / 32;

    // prologue: stage 0
#pragma unroll
    for (int u = 0; u < 4; u++) CP_ASYNC16(dA + u * 16, gA + u * 4);
#pragma unroll
    for (int u = 0; u < 4; u++) CP_ASYNC16(dB + u * 128, gB + u * 32);
    CP_COMMIT();

    for (int kt = 0; kt < nk; kt++) {
        int cur = kt & 1;
        if (kt + 1 < nk) {
            int nxt = cur ^ 1;
            const float* a = gA + (kt + 1) * 32;
            const float* b = gB + (size_t)(kt + 1) * 32 * N;
            uint32_t da = dA + (uint32_t)nxt * (ASTAGE * 4);
            uint32_t db = dB + (uint32_t)nxt * (BSTAGE * 4);
#pragma unroll
            for (int u = 0; u < 4; u++) CP_ASYNC16(da + u * 16, a + u * 4);
#pragma unroll
            for (int u = 0; u < 4; u++) CP_ASYNC16(db + u * 128, b + u * 32);
        }
        CP_COMMIT();
        CP_WAIT1();
        __syncthreads();

        const float* cA = sw + cur * ASTAGE;
        const float* cB = sw + 2 * ASTAGE + cur * BSTAGE;

#pragma unroll
        for (int ks = 0; ks < 4; ks++) {
            uint32_t af[2][4], bf[8][2];
#pragma unroll
            for (int mi = 0; mi < 2; mi++) {
                const float* p = cA + (m0 + mi * 16 + grp) * ASTRIDE + ks * 8 + ktid;
                af[mi][0] = f2tf32(p[0]);
                af[mi][1] = f2tf32(p[8 * ASTRIDE]);
                af[mi][2] = f2tf32(p[4]);
                af[mi][3] = f2tf32(p[8 * ASTRIDE + 4]);
            }
#pragma unroll
            for (int ni = 0; ni < 8; ni++) {
                const float* q = cB + (ks * 8 + ktid) * BSTRIDE + n0 + ni * 8 + grp;
                bf[ni][0] = f2tf32(q[0]);
                bf[ni][1] = f2tf32(q[4 * BSTRIDE]);
            }
#pragma unroll
            for (int mi = 0; mi < 2; mi++)
#pragma unroll
                for (int ni = 0; ni < 8; ni++)
                    MMA_TF32(acc[mi][ni], af[mi], bf[ni]);
        }
        __syncthreads();
    }

    // ---------------- epilogue ----------------
#pragma unroll
    for (int mi = 0; mi < 2; mi++) {
#pragma unroll
        for (int ni = 0; ni < 8; ni++) {
            int row = brow + m0 + mi * 16 + grp;
            int col = bcol + n0 + ni * 8 + ktid * 2;
            float b0v = 0.f, b1v = 0.f;
            if ((mode != 0) && bias) { b0v = bias[col]; b1v = bias[col + 1]; }
#pragma unroll
            for (int half = 0; half < 2; half++) {
                int r = row + half * 8;
                float v0 = acc[mi][ni][half * 2 + 0] + b0v;
                float v1 = acc[mi][ni][half * 2 + 1] + b1v;
                if (mode == 1 || mode == 2) { v0 = sigm(v0); v1 = sigm(v1); }
                size_t off = (size_t)r * N + col;
                if (mode == 2) {
                    float2 rr = *(const float2*)(resid + off);
                    v0 *= rr.x; v1 *= rr.y;
                } else if (mode == 3) {
                    float2 rr = *(const float2*)(resid + off);
                    v0 += rr.x; v1 += rr.y;
                }
                float2 o; o.x = v0; o.y = v1;
                *(float2*)(C + off) = o;
            }
        }
    }
}

// ---------------- chunked scan: h_t = r_t*h_{t-1} + yi_t ----------------
__global__ __launch_bounds__(256) void scan_pass1(const float* __restrict__ yi,
                                                  const float* __restrict__ rb,
                                                  float* __restrict__ Ac,
                                                  float* __restrict__ Sc) {
    int idx = blockIdx.x * 256 + threadIdx.x;
    int ch  = idx & 8191;
    int c   = idx >> 13;
    int b   = ch >> 11;
    int base = (b * 2048 + c * TCH) * 2048 + (ch & 2047);
    float A = 1.f, S = 0.f;
#pragma unroll 4
    for (int t = 0; t < TCH; t++) {
        float rr = rb[base];
        S = fmaf(rr, S, yi[base]);
        A *= rr;
        base += 2048;
    }
    Ac[idx] = A;
    Sc[idx] = S;
}

__global__ __launch_bounds__(256) void scan_pass2(const float* __restrict__ mem,
                                                  const float* __restrict__ Ac,
                                                  const float* __restrict__ Sc,
                                                  float* __restrict__ Hc,
                                                  float* __restrict__ memout) {
    int ch = blockIdx.x * 256 + threadIdx.x;
    float h = mem[ch];
#pragma unroll
    for (int c = 0; c < NCHUNK; c++) {
        int i = c * 8192 + ch;
        Hc[i] = h;
        h = fmaf(Ac[i], h, Sc[i]);
    }
    memout[ch] = h;
}

__global__ __launch_bounds__(256) void scan_pass3(const float* __restrict__ yi,
                                                  const float* __restrict__ rb,
                                                  const float* __restrict__ og,
                                                  const float* __restrict__ Hc,
                                                  float* __restrict__ g) {
    int idx = blockIdx.x * 256 + threadIdx.x;
    int ch  = idx & 8191;
    int c   = idx >> 13;
    int b   = ch >> 11;
    int base = (b * 2048 + c * TCH) * 2048 + (ch & 2047);
    float h = Hc[idx];
#pragma unroll 4
    for (int t = 0; t < TCH; t++) {
        float rr = rb[base];
        h = fmaf(rr, h, yi[base]);
        float s = h / (1.f + fabsf(h));
        g[base] = s * og[base];
        base += 2048;
    }
}

// ---------------- host launch ----------------
extern "C" void kernel_launch(void* const* d_in, const int* in_sizes, int n_in,
                              void* d_out, int out_size) {
    const float* x    = (const float*)d_in[0];
    const float* mem  = (const float*)d_in[1];
    const float* ln1w = (const float*)d_in[2];
    const float* ln1b = (const float*)d_in[3];
    const float* wf   = (const float*)d_in[4];
    const float* wfb  = (const float*)d_in[5];
    const float* wi   = (const float*)d_in[6];
    const float* wig  = (const float*)d_in[7];
    const float* wigb = (const float*)d_in[8];
    const float* wog  = (const float*)d_in[9];
    const float* wogb = (const float*)d_in[10];
    const float* wo   = (const float*)d_in[11];
    const float* ln2w = (const float*)d_in[12];
    const float* ln2b = (const float*)d_in[13];
    const float* fwi  = (const float*)d_in[14];
    const float* fwg  = (const float*)d_in[15];
    const float* fwgb = (const float*)d_in[16];
    const float* fwo  = (const float*)d_in[17];
    const float* fwob = (const float*)d_in[18];
    float* out = (float*)d_out;

    float *y, *b0, *b1, *rb, *og, *g, *x2, *z, *Ac, *Sc, *Hc;
    cudaGetSymbolAddress((void**)&y,  g_y);
    cudaGetSymbolAddress((void**)&b0, g_b0);
    cudaGetSymbolAddress((void**)&b1, g_b1);
    cudaGetSymbolAddress((void**)&rb, g_r);
    cudaGetSymbolAddress((void**)&og, g_og);
    cudaGetSymbolAddress((void**)&g,  g_g);
    cudaGetSymbolAddress((void**)&x2, g_x2);
    cudaGetSymbolAddress((void**)&z,  g_z);
    cudaGetSymbolAddress((void**)&Ac, g_Ac);
    cudaGetSymbolAddress((void**)&Sc, g_Sc);
    cudaGetSymbolAddress((void**)&Hc, g_Hc);

    cudaFuncSetAttribute(gemm_mma, cudaFuncAttributeMaxDynamicSharedMemorySize, GSMEM);

    ln1024<<<R_ROWS, 256>>>(x, ln1w, ln1b, y);

    dim3 gM(M_DIM / 128, R_ROWS / 128);
    dim3 gE(E_DIM / 128, R_ROWS / 128);

    gemm_mma<<<gM, 256, GSMEM>>>(y, wi,  nullptr, nullptr, b0, E_DIM, M_DIM, 0);
    gemm_mma<<<gM, 256, GSMEM>>>(y, wig, wigb,    b0,      b1, E_DIM, M_DIM, 2); // yi = b0*sig
    gemm_mma<<<gM, 256, GSMEM>>>(y, wf,  wfb,     nullptr, rb, E_DIM, M_DIM, 1);
    gemm_mma<<<gM, 256, GSMEM>>>(y, wog, wogb,    nullptr, og, E_DIM, M_DIM, 1);

    scan_pass1<<<NCHUNK * 8192 / 256, 256>>>(b1, rb, Ac, Sc);
    scan_pass2<<<8192 / 256, 256>>>(mem, Ac, Sc, Hc, out + (size_t)R_ROWS * E_DIM);
    scan_pass3<<<NCHUNK * 8192 / 256, 256>>>(b1, rb, og, Hc, g);

    gemm_mma<<<gE, 256, GSMEM>>>(g, wo, nullptr, x, x2, M_DIM, E_DIM, 3);

    ln1024<<<R_ROWS, 256>>>(x2, ln2w, ln2b, z);

    gemm_mma<<<gM, 256, GSMEM>>>(z,  fwi, nullptr, nullptr, b0,  E_DIM, M_DIM, 0);
    gemm_mma<<<gM, 256, GSMEM>>>(z,  fwg, fwgb,    b0,      b1,  E_DIM, M_DIM, 2); // zi
    gemm_mma<<<gE, 256, GSMEM>>>(b1, fwo, fwob,    x2,      out, M_DIM, E_DIM, 3);
}